// round 5
// baseline (speedup 1.0000x reference)
#include <cuda_runtime.h>
#include <cstdint>

#define N_NODES 4096
#define E_EDGES 262144
#define IN_DIM  256
#define NBOND   5
#define NATOM   16
#define LATENT  128

// Output layout (float32), tuple order (latent, atoms, bonds):
#define OFF_LATENT 0
#define OFF_ATOMS  524288
#define OFF_BONDS  589824

// ---------------------------------------------------------------------------
// Scratch
// ---------------------------------------------------------------------------
__device__ int   g_table[(size_t)N_NODES * N_NODES];   // 64 MB pair table
__device__ float g_s1[(size_t)N_NODES * IN_DIM];
__device__ float g_esym[(size_t)E_EDGES * 16];
__device__ int   g_jj[E_EDGES];
__device__ int   g_ii[E_EDGES];
__device__ int   g_flag;                               // 1 if edge_index is int64

// Packed fp32x2 helpers (FFMA2 — only reachable via PTX, see SASS patterns)
__device__ __forceinline__ void ffma2(unsigned long long& d,
                                      unsigned long long a, unsigned long long b) {
    asm("fma.rn.f32x2 %0, %1, %2, %0;" : "+l"(d) : "l"(a), "l"(b));
}
__device__ __forceinline__ float2 unpack2(unsigned long long v) {
    float2 r;
    asm("mov.b64 {%0, %1}, %2;" : "=f"(r.x), "=f"(r.y) : "l"(v));
    return r;
}

// ---------------------------------------------------------------------------
// Parallel dtype detect: int64 little-endian with values < 4096 has all odd
// 32-bit words zero.
// ---------------------------------------------------------------------------
__global__ void detect_kernel(const void* __restrict__ eidx) {
    const int* p = (const int*)eidx;
    int lane = threadIdx.x;
    int bad = (p[4 * lane + 1] != 0) | (p[4 * lane + 3] != 0);
    unsigned any_bad = __ballot_sync(0xffffffffu, bad);
    if (lane == 0) g_flag = (any_bad == 0u) ? 1 : 0;
}

// Convert indices to int32 AND clear the table entries we'll later read.
__global__ void convert_clear_kernel(const void* __restrict__ eidx) {
    int k = blockIdx.x * blockDim.x + threadIdx.x;
    if (k >= E_EDGES) return;
    int j, i;
    if (g_flag) {
        const long long* p = (const long long*)eidx;
        j = (int)p[k];
        i = (int)p[E_EDGES + k];
    } else {
        const int* p = (const int*)eidx;
        j = p[k];
        i = p[E_EDGES + k];
    }
    g_jj[k] = j;
    g_ii[k] = i;
    g_table[j * N_NODES + i] = -1;
    g_table[i * N_NODES + j] = -1;
}

// "Last write wins" scatter semantics via atomicMax on edge index.
__global__ void scatter_kernel() {
    int k = blockIdx.x * blockDim.x + threadIdx.x;
    if (k >= E_EDGES) return;
    atomicMax(&g_table[g_jj[k] * N_NODES + g_ii[k]], k);
}

// e_sym[k] = 0.5 * (e[fwd] + (rev >= 0 ? e[rev] : 0)); 2 edges per thread,
// all table reads issued before use.
__global__ void esym_kernel(const float* __restrict__ e) {
    int k0 = (blockIdx.x * blockDim.x + threadIdx.x) * 2;
    if (k0 >= E_EDGES) return;

    int j0 = g_jj[k0],     i0 = g_ii[k0];
    int j1 = g_jj[k0 + 1], i1 = g_ii[k0 + 1];
    int f0 = g_table[j0 * N_NODES + i0];
    int r0 = g_table[i0 * N_NODES + j0];
    int f1 = g_table[j1 * N_NODES + i1];
    int r1 = g_table[i1 * N_NODES + j1];

    #pragma unroll
    for (int u = 0; u < 2; u++) {
        int k = k0 + u;
        int f = u ? f1 : f0;
        int r = u ? r1 : r0;
        const float4* ef = (const float4*)(e + (size_t)f * 16);
        float4*       o  = (float4*)(g_esym + (size_t)k * 16);
        if (r >= 0) {
            const float4* er = (const float4*)(e + (size_t)r * 16);
            #pragma unroll
            for (int c = 0; c < 4; c++) {
                float4 a = ef[c], b = er[c];
                o[c] = make_float4(0.5f * (a.x + b.x), 0.5f * (a.y + b.y),
                                   0.5f * (a.z + b.z), 0.5f * (a.w + b.w));
            }
        } else {
            #pragma unroll
            for (int c = 0; c < 4; c++) {
                float4 a = ef[c];
                o[c] = make_float4(0.5f * a.x, 0.5f * a.y, 0.5f * a.z, 0.5f * a.w);
            }
        }
    }
}

// ---------------------------------------------------------------------------
// Tiled SGEMM: C[m][t] = act( sum_k A[m][k] * W[t][k] + bias[t] )
// ---------------------------------------------------------------------------
template <int SILU, int SPLIT>
__global__ void __launch_bounds__(256)
gemm_kernel(const float* __restrict__ A_in, const float* __restrict__ W,
            const float* __restrict__ bias, float* __restrict__ out, int T) {
    __shared__ float As[16][64];
    __shared__ float Ws[16][64];

    const float* A = SPLIT ? g_s1 : A_in;

    int tid = threadIdx.x;
    int tn = tid & 15;
    int tm = tid >> 4;
    int m0 = blockIdx.y * 64;
    int t0 = blockIdx.x * 64;

    int lr = tid >> 2;
    int lc = (tid & 3) * 4;

    float acc[4][4] = {};

    for (int k0 = 0; k0 < IN_DIM; k0 += 16) {
        float4 av = *(const float4*)(A + (size_t)(m0 + lr) * IN_DIM + k0 + lc);
        As[lc + 0][lr] = av.x; As[lc + 1][lr] = av.y;
        As[lc + 2][lr] = av.z; As[lc + 3][lr] = av.w;

        float4 wv = make_float4(0.f, 0.f, 0.f, 0.f);
        if (t0 + lr < T)
            wv = *(const float4*)(W + (size_t)(t0 + lr) * IN_DIM + k0 + lc);
        Ws[lc + 0][lr] = wv.x; Ws[lc + 1][lr] = wv.y;
        Ws[lc + 2][lr] = wv.z; Ws[lc + 3][lr] = wv.w;

        __syncthreads();

        #pragma unroll
        for (int kk = 0; kk < 16; kk++) {
            float4 a = *(const float4*)&As[kk][tm * 4];
            float4 w = *(const float4*)&Ws[kk][tn * 4];
            acc[0][0] += a.x * w.x; acc[0][1] += a.x * w.y; acc[0][2] += a.x * w.z; acc[0][3] += a.x * w.w;
            acc[1][0] += a.y * w.x; acc[1][1] += a.y * w.y; acc[1][2] += a.y * w.z; acc[1][3] += a.y * w.w;
            acc[2][0] += a.z * w.x; acc[2][1] += a.z * w.y; acc[2][2] += a.z * w.z; acc[2][3] += a.z * w.w;
            acc[3][0] += a.w * w.x; acc[3][1] += a.w * w.y; acc[3][2] += a.w * w.z; acc[3][3] += a.w * w.w;
        }
        __syncthreads();
    }

    #pragma unroll
    for (int u = 0; u < 4; u++) {
        int m = m0 + tm * 4 + u;
        #pragma unroll
        for (int v = 0; v < 4; v++) {
            int t = t0 + tn * 4 + v;
            if (t < T) {
                float x = acc[u][v] + bias[t];
                if (SILU) x = x * __fdividef(1.f, 1.f + __expf(-x));
                if (!SPLIT) {
                    g_s1[(size_t)m * 256 + t] = x;
                } else {
                    if (t < NATOM)
                        out[OFF_ATOMS + (size_t)m * NATOM + t] = x;
                    else
                        out[OFF_LATENT + (size_t)m * LATENT + (t - NATOM)] = x;
                }
            }
        }
    }
}

// ---------------------------------------------------------------------------
// Edge head, two-phase, latency-pipelined.
// Phase A (thread t = output dim): per 8-edge batch, issue ALL 16 s1 gathers
//   first (MLP=16, hides ~250cy L2 latency), then compute
//   f = silu(s1[j]+s1[i]+e_sym.Wbond^T+b) into smem fbuf.
// Phase B (160 threads, thread (b,q)): 256-dot from smem using packed
//   fma.rn.f32x2 (FFMA2), 2 floats per FMA.
// smem ~41 KB -> 5 blocks/SM; regs ~48.
// ---------------------------------------------------------------------------
#define EB   32
#define BATCH 8
#define FPAD 260
#define EPB  256

__global__ void __launch_bounds__(256)
edge_kernel(float* __restrict__ out_bonds,
            const float* __restrict__ W_bond, const float* __restrict__ b_bond,
            const float* __restrict__ W_bonds, const float* __restrict__ b_bonds) {
    int t = threadIdx.x;

    // Phase-A weights: W_bond row for dim t (16 regs)
    float wb[16];
    #pragma unroll
    for (int c = 0; c < 16; c += 4) {
        float4 v = *(const float4*)(W_bond + t * 16 + c);
        wb[c] = v.x; wb[c + 1] = v.y; wb[c + 2] = v.z; wb[c + 3] = v.w;
    }
    float bbias = b_bond[t];

    __shared__ __align__(16) float es[EB][16];       // 2 KB
    __shared__ int   sj[EB], si[EB];
    __shared__ __align__(16) float fbuf[EB][FPAD];   // 33.3 KB
    __shared__ __align__(16) float wqs[NBOND][FPAD]; // 5.2 KB

    // W_bonds -> smem (once per block)
    for (int idx = t; idx < NBOND * IN_DIM; idx += 256)
        wqs[idx >> 8][idx & 255] = W_bonds[idx];

    int base0 = blockIdx.x * EPB;

    for (int bb0 = 0; bb0 < EPB; bb0 += EB) {
        int base = base0 + bb0;

        if (t < EB) { sj[t] = g_jj[base + t]; si[t] = g_ii[base + t]; }
        ((float*)es)[t]       = g_esym[(size_t)base * 16 + t];
        ((float*)es)[t + 256] = g_esym[(size_t)base * 16 + 256 + t];
        __syncthreads();

        // Phase A in batches of 8 edges: all 16 gathers issued before use.
        #pragma unroll
        for (int b0 = 0; b0 < EB; b0 += BATCH) {
            float rj[BATCH], ri[BATCH];
            #pragma unroll
            for (int u = 0; u < BATCH; u++) {
                rj[u] = g_s1[sj[b0 + u] * IN_DIM + t];
                ri[u] = g_s1[si[b0 + u] * IN_DIM + t];
            }
            #pragma unroll
            for (int u = 0; u < BATCH; u++) {
                int b = b0 + u;
                float4 e0 = *(const float4*)&es[b][0];
                float4 e1 = *(const float4*)&es[b][4];
                float4 e2 = *(const float4*)&es[b][8];
                float4 e3 = *(const float4*)&es[b][12];

                float acc = bbias + rj[u] + ri[u];
                acc += e0.x * wb[0]  + e0.y * wb[1]  + e0.z * wb[2]  + e0.w * wb[3];
                acc += e1.x * wb[4]  + e1.y * wb[5]  + e1.z * wb[6]  + e1.w * wb[7];
                acc += e2.x * wb[8]  + e2.y * wb[9]  + e2.z * wb[10] + e2.w * wb[11];
                acc += e3.x * wb[12] + e3.y * wb[13] + e3.z * wb[14] + e3.w * wb[15];

                fbuf[b][t] = __fdividef(acc, 1.f + __expf(-acc));
            }
        }
        __syncthreads();

        // Phase B: 160 threads, thread (b,q) -> one 256-dot, packed f32x2
        if (t < EB * NBOND) {
            int b = t / NBOND, q = t - b * NBOND;
            const ulonglong2* fr = (const ulonglong2*)&fbuf[b][0];
            const ulonglong2* wr = (const ulonglong2*)&wqs[q][0];
            unsigned long long a0 = 0ull, a1 = 0ull;   // {0.f,0.f} packed
            #pragma unroll
            for (int c = 0; c < 64; c++) {
                ulonglong2 fv = fr[c];
                ulonglong2 wv = wr[c];
                ffma2(a0, fv.x, wv.x);
                ffma2(a1, fv.y, wv.y);
            }
            float2 s0 = unpack2(a0), s1v = unpack2(a1);
            out_bonds[(size_t)(base + b) * NBOND + q] =
                s0.x + s0.y + s1v.x + s1v.y + b_bonds[q];
        }
        __syncthreads();
    }
}

// ---------------------------------------------------------------------------
// Launch
// ---------------------------------------------------------------------------
extern "C" void kernel_launch(void* const* d_in, const int* in_sizes, int n_in,
                              void* d_out, int out_size) {
    const float* s        = (const float*)d_in[0];
    const float* e        = (const float*)d_in[1];
    // d_in[2] = batch (unused)
    const void*  eidx     = d_in[3];
    const float* W_shared = (const float*)d_in[4];
    const float* b_shared = (const float*)d_in[5];
    const float* W_bond   = (const float*)d_in[6];
    const float* b_bond   = (const float*)d_in[7];
    const float* W_bonds  = (const float*)d_in[8];
    const float* b_bonds  = (const float*)d_in[9];
    const float* W_atoms  = (const float*)d_in[10];
    const float* b_atoms  = (const float*)d_in[11];
    float* out = (float*)d_out;

    const int tpb = 256;
    const int eblocks = E_EDGES / tpb;   // 1024

    detect_kernel<<<1, 32>>>(eidx);
    convert_clear_kernel<<<eblocks, tpb>>>(eidx);
    scatter_kernel<<<eblocks, tpb>>>();
    esym_kernel<<<eblocks / 2, tpb>>>(e);

    gemm_kernel<1, 0><<<dim3(4, 64), 256>>>(s, W_shared, b_shared, out, 256);
    gemm_kernel<0, 1><<<dim3(3, 64), 256>>>(nullptr, W_atoms, b_atoms, out, 144);

    edge_kernel<<<E_EDGES / EPB, 256>>>(out + OFF_BONDS,
                                        W_bond, b_bond, W_bonds, b_bonds);
}

// round 6
// speedup vs baseline: 1.0484x; 1.0484x over previous
#include <cuda_runtime.h>
#include <cstdint>

#define N_NODES 4096
#define E_EDGES 262144
#define IN_DIM  256
#define NBOND   5
#define NATOM   16
#define LATENT  128

// Output layout (float32), tuple order (latent, atoms, bonds):
#define OFF_LATENT 0
#define OFF_ATOMS  524288
#define OFF_BONDS  589824

// ---------------------------------------------------------------------------
// Scratch
// ---------------------------------------------------------------------------
__device__ int   g_table[(size_t)N_NODES * N_NODES];   // 64 MB pair table
__device__ float g_s1[(size_t)N_NODES * IN_DIM];
__device__ float g_esym[(size_t)E_EDGES * 16];
__device__ int   g_jj[E_EDGES];
__device__ int   g_ii[E_EDGES];
__device__ int   g_flag;                               // 1 if edge_index is int64

// Packed fp32x2 helpers (FFMA2 — only reachable via PTX)
__device__ __forceinline__ void ffma2(unsigned long long& d,
                                      unsigned long long a, unsigned long long b) {
    asm("fma.rn.f32x2 %0, %1, %2, %0;" : "+l"(d) : "l"(a), "l"(b));
}
__device__ __forceinline__ float2 unpack2(unsigned long long v) {
    float2 r;
    asm("mov.b64 {%0, %1}, %2;" : "=f"(r.x), "=f"(r.y) : "l"(v));
    return r;
}
__device__ __forceinline__ unsigned long long pack2(float lo, float hi) {
    unsigned long long r;
    asm("mov.b64 %0, {%1, %2};" : "=l"(r) : "f"(lo), "f"(hi));
    return r;
}

// ---------------------------------------------------------------------------
// Parallel dtype detect
// ---------------------------------------------------------------------------
__global__ void detect_kernel(const void* __restrict__ eidx) {
    const int* p = (const int*)eidx;
    int lane = threadIdx.x;
    int bad = (p[4 * lane + 1] != 0) | (p[4 * lane + 3] != 0);
    unsigned any_bad = __ballot_sync(0xffffffffu, bad);
    if (lane == 0) g_flag = (any_bad == 0u) ? 1 : 0;
}

// Convert indices to int32 AND clear the table entries we'll later read.
__global__ void convert_clear_kernel(const void* __restrict__ eidx) {
    int k = blockIdx.x * blockDim.x + threadIdx.x;
    if (k >= E_EDGES) return;
    int j, i;
    if (g_flag) {
        const long long* p = (const long long*)eidx;
        j = (int)p[k];
        i = (int)p[E_EDGES + k];
    } else {
        const int* p = (const int*)eidx;
        j = p[k];
        i = p[E_EDGES + k];
    }
    g_jj[k] = j;
    g_ii[k] = i;
    g_table[j * N_NODES + i] = -1;
    g_table[i * N_NODES + j] = -1;
}

// "Last write wins" scatter via atomicMax on edge index.
__global__ void scatter_kernel() {
    int k = blockIdx.x * blockDim.x + threadIdx.x;
    if (k >= E_EDGES) return;
    atomicMax(&g_table[g_jj[k] * N_NODES + g_ii[k]], k);
}

// e_sym[k] = 0.5 * (e[fwd] + (rev >= 0 ? e[rev] : 0)); 1 edge/thread,
// grid 1024 for full occupancy.
__global__ void esym_kernel(const float* __restrict__ e) {
    int k = blockIdx.x * blockDim.x + threadIdx.x;
    if (k >= E_EDGES) return;
    int j = g_jj[k], i = g_ii[k];
    int f = g_table[j * N_NODES + i];
    int r = g_table[i * N_NODES + j];
    const float4* ef = (const float4*)(e + (size_t)f * 16);
    float4*       o  = (float4*)(g_esym + (size_t)k * 16);
    if (r >= 0) {
        const float4* er = (const float4*)(e + (size_t)r * 16);
        #pragma unroll
        for (int c = 0; c < 4; c++) {
            float4 a = ef[c], b = er[c];
            o[c] = make_float4(0.5f * (a.x + b.x), 0.5f * (a.y + b.y),
                               0.5f * (a.z + b.z), 0.5f * (a.w + b.w));
        }
    } else {
        #pragma unroll
        for (int c = 0; c < 4; c++) {
            float4 a = ef[c];
            o[c] = make_float4(0.5f * a.x, 0.5f * a.y, 0.5f * a.z, 0.5f * a.w);
        }
    }
}

// ---------------------------------------------------------------------------
// Tiled SGEMM: C[m][t] = act( sum_k A[m][k] * W[t][k] + bias[t] )
// ---------------------------------------------------------------------------
template <int SILU, int SPLIT>
__global__ void __launch_bounds__(256)
gemm_kernel(const float* __restrict__ A_in, const float* __restrict__ W,
            const float* __restrict__ bias, float* __restrict__ out, int T) {
    __shared__ float As[16][64];
    __shared__ float Ws[16][64];

    const float* A = SPLIT ? g_s1 : A_in;

    int tid = threadIdx.x;
    int tn = tid & 15;
    int tm = tid >> 4;
    int m0 = blockIdx.y * 64;
    int t0 = blockIdx.x * 64;

    int lr = tid >> 2;
    int lc = (tid & 3) * 4;

    float acc[4][4] = {};

    for (int k0 = 0; k0 < IN_DIM; k0 += 16) {
        float4 av = *(const float4*)(A + (size_t)(m0 + lr) * IN_DIM + k0 + lc);
        As[lc + 0][lr] = av.x; As[lc + 1][lr] = av.y;
        As[lc + 2][lr] = av.z; As[lc + 3][lr] = av.w;

        float4 wv = make_float4(0.f, 0.f, 0.f, 0.f);
        if (t0 + lr < T)
            wv = *(const float4*)(W + (size_t)(t0 + lr) * IN_DIM + k0 + lc);
        Ws[lc + 0][lr] = wv.x; Ws[lc + 1][lr] = wv.y;
        Ws[lc + 2][lr] = wv.z; Ws[lc + 3][lr] = wv.w;

        __syncthreads();

        #pragma unroll
        for (int kk = 0; kk < 16; kk++) {
            float4 a = *(const float4*)&As[kk][tm * 4];
            float4 w = *(const float4*)&Ws[kk][tn * 4];
            acc[0][0] += a.x * w.x; acc[0][1] += a.x * w.y; acc[0][2] += a.x * w.z; acc[0][3] += a.x * w.w;
            acc[1][0] += a.y * w.x; acc[1][1] += a.y * w.y; acc[1][2] += a.y * w.z; acc[1][3] += a.y * w.w;
            acc[2][0] += a.z * w.x; acc[2][1] += a.z * w.y; acc[2][2] += a.z * w.z; acc[2][3] += a.z * w.w;
            acc[3][0] += a.w * w.x; acc[3][1] += a.w * w.y; acc[3][2] += a.w * w.z; acc[3][3] += a.w * w.w;
        }
        __syncthreads();
    }

    #pragma unroll
    for (int u = 0; u < 4; u++) {
        int m = m0 + tm * 4 + u;
        #pragma unroll
        for (int v = 0; v < 4; v++) {
            int t = t0 + tn * 4 + v;
            if (t < T) {
                float x = acc[u][v] + bias[t];
                if (SILU) x = x * __fdividef(1.f, 1.f + __expf(-x));
                if (!SPLIT) {
                    g_s1[(size_t)m * 256 + t] = x;
                } else {
                    if (t < NATOM)
                        out[OFF_ATOMS + (size_t)m * NATOM + t] = x;
                    else
                        out[OFF_LATENT + (size_t)m * LATENT + (t - NATOM)] = x;
                }
            }
        }
    }
}

// ---------------------------------------------------------------------------
// Edge head, two-phase, packed f32x2 phase A.
// 128 threads/block; thread t owns dims (2t, 2t+1).
// Phase A: f{2t,2t+1} = silu(s1[j]+s1[i]+esym.Wbond^T+b) with 16 FFMA2
//   (weight pairs in regs, esym dup-packed in smem), LDG.64 gathers, STS.64.
// Phase B: 80 threads, thread (b,q) -> 256-dot from smem with FFMA2.
// ---------------------------------------------------------------------------
#define EB   16
#define BATCH 4
#define FPAD 260
#define EPB  128

__global__ void __launch_bounds__(128)
edge_kernel(float* __restrict__ out_bonds,
            const float* __restrict__ W_bond, const float* __restrict__ b_bond,
            const float* __restrict__ W_bonds, const float* __restrict__ b_bonds) {
    int t = threadIdx.x;     // 0..127, dims 2t and 2t+1

    // Packed weight pairs for dims (2t, 2t+1): wb2[c] = {W[2t][c], W[2t+1][c]}
    unsigned long long wb2[16];
    #pragma unroll
    for (int c = 0; c < 16; c++)
        wb2[c] = pack2(W_bond[(2 * t) * 16 + c], W_bond[(2 * t + 1) * 16 + c]);
    float2 bb2 = ((const float2*)b_bond)[t];

    __shared__ __align__(16) unsigned long long esp[EB][16];  // dup-packed esym, 2 KB
    __shared__ int   sj[EB], si[EB];
    __shared__ __align__(16) float fbuf[EB][FPAD];            // 16.6 KB
    __shared__ __align__(16) float wqs[NBOND][FPAD];          // 5.2 KB

    // W_bonds -> smem (once per block)
    for (int idx = t; idx < NBOND * IN_DIM; idx += 128)
        wqs[idx >> 8][idx & 255] = W_bonds[idx];

    int base0 = blockIdx.x * EPB;

    for (int bb0 = 0; bb0 < EPB; bb0 += EB) {
        int base = base0 + bb0;

        if (t < EB) { sj[t] = g_jj[base + t]; si[t] = g_ii[base + t]; }
        // dup-pack esym for this tile: 256 scalars, 2 per thread
        {
            float v0 = g_esym[(size_t)base * 16 + t];
            float v1 = g_esym[(size_t)base * 16 + 128 + t];
            ((unsigned long long*)esp)[t]       = pack2(v0, v0);
            ((unsigned long long*)esp)[t + 128] = pack2(v1, v1);
        }
        __syncthreads();

        #pragma unroll
        for (int b0 = 0; b0 < EB; b0 += BATCH) {
            float2 rj[BATCH], ri[BATCH];
            #pragma unroll
            for (int u = 0; u < BATCH; u++) {
                rj[u] = ((const float2*)(g_s1 + (size_t)sj[b0 + u] * IN_DIM))[t];
                ri[u] = ((const float2*)(g_s1 + (size_t)si[b0 + u] * IN_DIM))[t];
            }
            #pragma unroll
            for (int u = 0; u < BATCH; u++) {
                int b = b0 + u;
                unsigned long long acc = 0ull;   // {0.f, 0.f}
                #pragma unroll
                for (int c = 0; c < 16; c++)
                    ffma2(acc, esp[b][c], wb2[c]);
                float2 a = unpack2(acc);
                float x0 = a.x + rj[u].x + ri[u].x + bb2.x;
                float x1 = a.y + rj[u].y + ri[u].y + bb2.y;
                float f0 = __fdividef(x0, 1.f + __expf(-x0));
                float f1 = __fdividef(x1, 1.f + __expf(-x1));
                *(float2*)&fbuf[b][2 * t] = make_float2(f0, f1);
            }
        }
        __syncthreads();

        // Phase B: 80 threads, thread (b,q) -> one 256-dot, packed f32x2
        if (t < EB * NBOND) {
            int b = t / NBOND, q = t - b * NBOND;
            const ulonglong2* fr = (const ulonglong2*)&fbuf[b][0];
            const ulonglong2* wr = (const ulonglong2*)&wqs[q][0];
            unsigned long long a0 = 0ull, a1 = 0ull;
            #pragma unroll
            for (int c = 0; c < 64; c++) {
                ulonglong2 fv = fr[c];
                ulonglong2 wv = wr[c];
                ffma2(a0, fv.x, wv.x);
                ffma2(a1, fv.y, wv.y);
            }
            float2 s0 = unpack2(a0), s1v = unpack2(a1);
            out_bonds[(size_t)(base + b) * NBOND + q] =
                s0.x + s0.y + s1v.x + s1v.y + b_bonds[q];
        }
        __syncthreads();
    }
}

// ---------------------------------------------------------------------------
// Launch: fork GEMM chain onto a side stream, join before edge_kernel.
// ---------------------------------------------------------------------------
extern "C" void kernel_launch(void* const* d_in, const int* in_sizes, int n_in,
                              void* d_out, int out_size) {
    const float* s        = (const float*)d_in[0];
    const float* e        = (const float*)d_in[1];
    // d_in[2] = batch (unused)
    const void*  eidx     = d_in[3];
    const float* W_shared = (const float*)d_in[4];
    const float* b_shared = (const float*)d_in[5];
    const float* W_bond   = (const float*)d_in[6];
    const float* b_bond   = (const float*)d_in[7];
    const float* W_bonds  = (const float*)d_in[8];
    const float* b_bonds  = (const float*)d_in[9];
    const float* W_atoms  = (const float*)d_in[10];
    const float* b_atoms  = (const float*)d_in[11];
    float* out = (float*)d_out;

    const int tpb = 256;
    const int eblocks = E_EDGES / tpb;   // 1024

    cudaStream_t s2;
    cudaStreamCreateWithFlags(&s2, cudaStreamNonBlocking);
    cudaEvent_t ef, ej;
    cudaEventCreateWithFlags(&ef, cudaEventDisableTiming);
    cudaEventCreateWithFlags(&ej, cudaEventDisableTiming);

    // fork: GEMM chain on s2 (independent of edge prep)
    cudaEventRecord(ef, 0);
    cudaStreamWaitEvent(s2, ef, 0);
    gemm_kernel<1, 0><<<dim3(4, 64), 256, 0, s2>>>(s, W_shared, b_shared, out, 256);
    gemm_kernel<0, 1><<<dim3(3, 64), 256, 0, s2>>>(nullptr, W_atoms, b_atoms, out, 144);
    cudaEventRecord(ej, s2);

    // edge prep chain on default stream
    detect_kernel<<<1, 32>>>(eidx);
    convert_clear_kernel<<<eblocks, tpb>>>(eidx);
    scatter_kernel<<<eblocks, tpb>>>();
    esym_kernel<<<eblocks, tpb>>>(e);

    // join: edge kernel needs g_s1 (gemm1) + g_esym
    cudaStreamWaitEvent(0, ej, 0);
    edge_kernel<<<E_EDGES / EPB, 128>>>(out + OFF_BONDS,
                                        W_bond, b_bond, W_bonds, b_bonds);

    cudaEventDestroy(ef);
    cudaEventDestroy(ej);
    cudaStreamDestroy(s2);
}